// round 11
// baseline (speedup 1.0000x reference)
#include <cuda_runtime.h>

#define B_   32
#define M_   64
#define A_   8400
#define TK   9
#define NC   80
#define EPSF 1e-9f

// Scratch (allocation-free). Packed per-anchor tag: bits[31:16] = positive
// count, bits[15:0] = sum of (m+1). count<=64, sum(m+1)<=4096 -> no overflow
// between fields; when count==1 the low half is exactly m+1.
// INVARIANT: zero at module load (CUDA zero-init), and the assign kernel
// re-zeroes each element after consuming it, so every launch (and every graph
// replay) starts from zero -> no init kernel needed.
__device__ int g_tag[B_ * A_];

__device__ __forceinline__ float iou_box(float gx1, float gy1, float gx2, float gy2,
                                         float bx1, float by1, float bx2, float by2) {
    // matches reference _iou: b1 = gt, b2 = other; denom = a1 + a2 - overlap + EPS
    float ix1 = fmaxf(gx1, bx1), iy1 = fmaxf(gy1, by1);
    float ix2 = fminf(gx2, bx2), iy2 = fminf(gy2, by2);
    float ov  = fmaxf(ix2 - ix1, 0.f) * fmaxf(iy2 - iy1, 0.f);
    float a1  = fmaxf(gx2 - gx1, 0.f) * fmaxf(gy2 - gy1, 0.f);
    float a2  = fmaxf(bx2 - bx1, 0.f) * fmaxf(by2 - by1, 0.f);
    return ov / (a1 + a2 - ov + EPSF);
}

// One WARP per (b,m). Anchors are regular grids, so the top-9-by-center-distance
// per FPN level is contained in the 5x5 grid window around the gt center
// (9th-nearest lattice distance <= 1.581*stride < 2.0*stride = min excluded
// distance). Selection = 9 rounds of warp-min over u64 (d2,idx) keys — exact
// lax.top_k tie-break (d2-order refines sqrt-order; only the SET is consumed).
// thr = mean + std(ddof=1) over the 27 candidate IoUs, sequential order r=0..26
// (bit-identical to the R4/R5 passing kernels). Positives scatter one packed atomic.
__global__ void __launch_bounds__(256) atss_topk_kernel(
    const float* __restrict__ anchors,    // [A,4]
    const float* __restrict__ gt_bboxes,  // [B,M,4]
    const float* __restrict__ pad_mask)   // [B,M,1]
{
    const int warp = threadIdx.x >> 5;
    const int lane = threadIdx.x & 31;
    const int wid  = blockIdx.x * 8 + warp;   // (b,m) flat, 2048 total
    const int b = wid >> 6;
    const int m = wid & 63;

    if (pad_mask[wid] <= 0.f) return;         // warp-uniform

    const float4 g = ((const float4*)gt_bboxes)[wid];
    const float gcx = (g.x + g.z) * 0.5f;
    const float gcy = (g.y + g.w) * 0.5f;

    const int   FS[3]   = {80, 40, 20};
    const float INV[3]  = {0.125f, 0.0625f, 0.03125f};  // 1/stride (exact pow2)
    const int   BASE[3] = {0, 6400, 8000};

    int my_win = 0;          // lane r (< 27) ends up holding winner lvl*9 + r
    bool have_win = false;

    #pragma unroll
    for (int lvl = 0; lvl < 3; lvl++) {
        const int fs = FS[lvl];
        const int base = BASE[lvl];
        int jx0 = (int)floorf(gcx * INV[lvl] - 0.5f) - 2;
        int iy0 = (int)floorf(gcy * INV[lvl] - 0.5f) - 2;
        jx0 = min(max(jx0, 0), fs - 5);
        iy0 = min(max(iy0, 0), fs - 5);

        unsigned long long key = ~0ull;
        if (lane < 25) {
            const int idx = base + (iy0 + lane / 5) * fs + (jx0 + lane % 5);
            float4 ab = ((const float4*)anchors)[idx];
            float acx = (ab.x + ab.z) * 0.5f;
            float acy = (ab.y + ab.w) * 0.5f;
            float dx = gcx - acx, dy = gcy - acy;
            float d2 = dx * dx + dy * dy;       // nonneg -> bit pattern is order-preserving
            key = ((unsigned long long)__float_as_uint(d2) << 32) | (unsigned)idx;
        }

        #pragma unroll
        for (int r = 0; r < TK; r++) {
            unsigned long long mn = key;
            #pragma unroll
            for (int off = 16; off; off >>= 1) {
                unsigned long long o = __shfl_xor_sync(0xffffffffu, mn, off);
                if (o < mn) mn = o;
            }
            if (key == mn) key = ~0ull;         // winner drops out (keys unique)
            if (lane == lvl * TK + r) { my_win = (int)(mn & 0xffffffffu); have_win = true; }
        }
    }

    // IoU of the 27 winners with the gt box
    float my_iou = 0.f;
    float4 ab = make_float4(0.f, 0.f, 0.f, 0.f);
    if (have_win) {
        ab = ((const float4*)anchors)[my_win];
        my_iou = iou_box(g.x, g.y, g.z, g.w, ab.x, ab.y, ab.z, ab.w);
    }

    // mean + std (ddof=1), sequential order r = 0..26 (matches prior passing kernel)
    float mean = 0.f;
    #pragma unroll
    for (int r = 0; r < 27; r++) mean += __shfl_sync(0xffffffffu, my_iou, r);
    mean *= (1.f / 27.f);
    float var = 0.f;
    #pragma unroll
    for (int r = 0; r < 27; r++) {
        float v = __shfl_sync(0xffffffffu, my_iou, r) - mean;
        var += v * v;
    }
    const float thr = mean + sqrtf(var * (1.f / 26.f));

    if (have_win && my_iou > thr) {
        float acx = (ab.x + ab.z) * 0.5f;
        float acy = (ab.y + ab.w) * 0.5f;
        float lmin = fminf(fminf(acx - g.x, acy - g.y), fminf(g.z - acx, g.w - acy));
        if (lmin > EPSF) {                      // is_in_gts (strict > EPS)
            atomicAdd(&g_tag[b * A_ + my_win], 0x10000 + m + 1);
        }
    }
}

// Slim finalize (scores region already zeroed by the memset node):
// thread-per-anchor. Consume + re-zero g_tag, resolve multi-assignment
// (argmax anchor-IoU over all 64 gts, first-max ties), write labels + bboxes,
// and ONE scattered score store per positive anchor. ~8 MB total traffic.
__global__ void __launch_bounds__(256) atss_assign_kernel(
    const float* __restrict__ anchors,    // [A,4]
    const int*   __restrict__ gt_labels,  // [B,M]
    const float* __restrict__ gt_bboxes,  // [B,M,4]
    const float* __restrict__ pred,       // [B,A,4]
    const int*   __restrict__ bg_ptr,     // [1] or null
    float*       __restrict__ out)
{
    const int b = blockIdx.y;
    const int t = threadIdx.x;
    const int a = blockIdx.x * 256 + t;

    __shared__ float4 s_gt[M_];
    __shared__ int    s_lab[M_];
    if (t < M_) {
        s_gt[t]  = ((const float4*)gt_bboxes)[b * M_ + t];
        s_lab[t] = gt_labels[b * M_ + t];
    }
    __syncthreads();

    if (a >= A_) return;
    const long long OFF1 = (long long)B_ * A_;            // bboxes offset
    const long long OFF2 = OFF1 + (long long)B_ * A_ * 4; // scores offset
    const long long ba = (long long)b * A_ + a;
    const int bg = bg_ptr ? bg_ptr[0] : NC;

    const int tag = g_tag[ba];
    if (tag) g_tag[ba] = 0;                 // restore zero invariant for next replay
    const int cnt = tag >> 16;
    int asg = (cnt == 1) ? (tag & 0xffff) - 1 : 0;

    if (cnt > 1) {
        // mask_multi -> is_max_iou column: argmax over m of anchor-iou, first-max ties
        float4 ab = ((const float4*)anchors)[a];
        float best = -1.f; int bm = 0;
        #pragma unroll 4
        for (int mm = 0; mm < M_; mm++) {
            float4 gg = s_gt[mm];
            float v = iou_box(gg.x, gg.y, gg.z, gg.w, ab.x, ab.y, ab.z, ab.w);
            if (v > best) { best = v; bm = mm; }
        }
        asg = bm;
    }

    int   label = bg;
    float sval  = 0.f;
    if (cnt > 0) {
        label = s_lab[asg];
        float4 p = ((const float4*)pred)[ba];
        float4 gg = s_gt[asg];
        sval = iou_box(gg.x, gg.y, gg.z, gg.w, p.x, p.y, p.z, p.w);
    }

    out[ba] = (float)label;                  // assigned_labels (as f32)
    ((float4*)(out + OFF1))[ba] = s_gt[asg]; // assigned_bboxes (gt[0] when bg)
    if (cnt > 0 && label >= 0 && label < NC)
        out[OFF2 + ba * NC + label] = sval;  // one-hot * max(pious)
}

extern "C" void kernel_launch(void* const* d_in, const int* in_sizes, int n_in,
                              void* d_out, int out_size) {
    const float* anchors   = (const float*)d_in[0];
    const int*   gt_labels = (const int*)d_in[1];
    const float* gt_bboxes = (const float*)d_in[2];
    const float* pad_mask  = (const float*)d_in[3];
    const float* pred      = (const float*)d_in[4];
    const int*   bg_ptr    = (n_in > 5) ? (const int*)d_in[5] : nullptr;
    float* out = (float*)d_out;

    // Zero the 86 MB scores region with a memset node (stream-ordered,
    // graph-capturable) — driver fill path, no SASS instruction bottleneck.
    const long long OFF2 = (long long)B_ * A_ * 5;        // labels + bboxes
    cudaMemsetAsync(out + OFF2, 0, (size_t)B_ * A_ * NC * sizeof(float), 0);

    atss_topk_kernel<<<(B_ * M_) / 8, 256>>>(anchors, gt_bboxes, pad_mask);
    atss_assign_kernel<<<dim3((A_ + 255) / 256, B_), 256>>>(
        anchors, gt_labels, gt_bboxes, pred, bg_ptr, out);
}

// round 12
// speedup vs baseline: 1.5679x; 1.5679x over previous
#include <cuda_runtime.h>

#define B_   32
#define M_   64
#define A_   8400
#define TK   9
#define NC   80
#define EPSF 1e-9f

// Scratch (allocation-free). Packed per-anchor tag: bits[31:16] = positive
// count, bits[15:0] = sum of (m+1). count<=64, sum(m+1)<=4096 -> no overflow
// between fields; when count==1 the low half is exactly m+1.
// INVARIANT: zero at module load (CUDA zero-init); the assign kernel re-zeroes
// each element after consuming it, so every graph replay starts from zero.
__device__ int g_tag[B_ * A_];

__device__ __forceinline__ float iou_box(float gx1, float gy1, float gx2, float gy2,
                                         float bx1, float by1, float bx2, float by2) {
    // matches reference _iou: b1 = gt, b2 = other; denom = a1 + a2 - overlap + EPS
    float ix1 = fmaxf(gx1, bx1), iy1 = fmaxf(gy1, by1);
    float ix2 = fminf(gx2, bx2), iy2 = fminf(gy2, by2);
    float ov  = fmaxf(ix2 - ix1, 0.f) * fmaxf(iy2 - iy1, 0.f);
    float a1  = fmaxf(gx2 - gx1, 0.f) * fmaxf(gy2 - gy1, 0.f);
    float a2  = fmaxf(bx2 - bx1, 0.f) * fmaxf(by2 - by1, 0.f);
    return ov / (a1 + a2 - ov + EPSF);
}

// One WARP per (b,m). Anchors are regular grids, so the top-9-by-center-distance
// per FPN level is contained in the 5x5 grid window around the gt center.
// Selection = 9 rounds of warp-min over u64 (d2,idx) keys — exact lax.top_k
// tie-break. thr = mean + std(ddof=1) over the 27 candidate IoUs, sequential
// order r=0..26 (bit-identical to all prior passing kernels).
__global__ void __launch_bounds__(256) atss_topk_kernel(
    const float* __restrict__ anchors,    // [A,4]
    const float* __restrict__ gt_bboxes,  // [B,M,4]
    const float* __restrict__ pad_mask)   // [B,M,1]
{
    const int warp = threadIdx.x >> 5;
    const int lane = threadIdx.x & 31;
    const int wid  = blockIdx.x * 8 + warp;   // (b,m) flat, 2048 total
    const int b = wid >> 6;
    const int m = wid & 63;

    if (pad_mask[wid] <= 0.f) return;         // warp-uniform

    const float4 g = ((const float4*)gt_bboxes)[wid];
    const float gcx = (g.x + g.z) * 0.5f;
    const float gcy = (g.y + g.w) * 0.5f;

    const int   FS[3]   = {80, 40, 20};
    const float INV[3]  = {0.125f, 0.0625f, 0.03125f};  // 1/stride (exact pow2)
    const int   BASE[3] = {0, 6400, 8000};

    int my_win = 0;          // lane r (< 27) ends up holding winner lvl*9 + r
    bool have_win = false;

    #pragma unroll
    for (int lvl = 0; lvl < 3; lvl++) {
        const int fs = FS[lvl];
        const int base = BASE[lvl];
        int jx0 = (int)floorf(gcx * INV[lvl] - 0.5f) - 2;
        int iy0 = (int)floorf(gcy * INV[lvl] - 0.5f) - 2;
        jx0 = min(max(jx0, 0), fs - 5);
        iy0 = min(max(iy0, 0), fs - 5);

        unsigned long long key = ~0ull;
        if (lane < 25) {
            const int idx = base + (iy0 + lane / 5) * fs + (jx0 + lane % 5);
            float4 ab = ((const float4*)anchors)[idx];
            float acx = (ab.x + ab.z) * 0.5f;
            float acy = (ab.y + ab.w) * 0.5f;
            float dx = gcx - acx, dy = gcy - acy;
            float d2 = dx * dx + dy * dy;       // nonneg -> bit pattern is order-preserving
            key = ((unsigned long long)__float_as_uint(d2) << 32) | (unsigned)idx;
        }

        #pragma unroll
        for (int r = 0; r < TK; r++) {
            unsigned long long mn = key;
            #pragma unroll
            for (int off = 16; off; off >>= 1) {
                unsigned long long o = __shfl_xor_sync(0xffffffffu, mn, off);
                if (o < mn) mn = o;
            }
            if (key == mn) key = ~0ull;         // winner drops out (keys unique)
            if (lane == lvl * TK + r) { my_win = (int)(mn & 0xffffffffu); have_win = true; }
        }
    }

    float my_iou = 0.f;
    float4 ab = make_float4(0.f, 0.f, 0.f, 0.f);
    if (have_win) {
        ab = ((const float4*)anchors)[my_win];
        my_iou = iou_box(g.x, g.y, g.z, g.w, ab.x, ab.y, ab.z, ab.w);
    }

    float mean = 0.f;
    #pragma unroll
    for (int r = 0; r < 27; r++) mean += __shfl_sync(0xffffffffu, my_iou, r);
    mean *= (1.f / 27.f);
    float var = 0.f;
    #pragma unroll
    for (int r = 0; r < 27; r++) {
        float v = __shfl_sync(0xffffffffu, my_iou, r) - mean;
        var += v * v;
    }
    const float thr = mean + sqrtf(var * (1.f / 26.f));

    if (have_win && my_iou > thr) {
        float acx = (ab.x + ab.z) * 0.5f;
        float acy = (ab.y + ab.w) * 0.5f;
        float lmin = fminf(fminf(acx - g.x, acy - g.y), fminf(g.z - acx, g.w - acy));
        if (lmin > EPSF) {                      // is_in_gts (strict > EPS)
            atomicAdd(&g_tag[b * A_ + my_win], 0x10000 + m + 1);
        }
    }
}

// Fused finalize. Phase 1 (thread-per-anchor): consume + re-zero g_tag; resolve
// multi-assigned anchors WARP-COOPERATIVELY (ballot conflicted lanes, then the
// whole warp computes the 64-GT IoU argmax for each: 2 GTs/lane + u64 key
// min-reduce; key = (~iou_bits, m) reproduces first-max-over-m tie-break).
// Phase 2: stream complete one-hot score rows as coalesced float4 stores.
__global__ void __launch_bounds__(256) atss_assign_kernel(
    const float* __restrict__ anchors,    // [A,4]
    const int*   __restrict__ gt_labels,  // [B,M]
    const float* __restrict__ gt_bboxes,  // [B,M,4]
    const float* __restrict__ pred,       // [B,A,4]
    const int*   __restrict__ bg_ptr,     // [1] or null
    float*       __restrict__ out)
{
    const int b    = blockIdx.y;
    const int t    = threadIdx.x;
    const int lane = t & 31;
    const int a0   = blockIdx.x * 256;
    const int a    = a0 + t;
    const bool valid = a < A_;

    __shared__ float4 s_gt[M_];
    __shared__ int    s_lab[M_];
    __shared__ int    s_alab[256];   // assigned label, or -1 when score row is all-zero
    __shared__ float  s_sval[256];

    if (t < M_) {
        s_gt[t]  = ((const float4*)gt_bboxes)[b * M_ + t];
        s_lab[t] = gt_labels[b * M_ + t];
    }
    __syncthreads();

    const long long OFF1 = (long long)B_ * A_;            // bboxes offset
    const long long OFF2 = OFF1 + (long long)B_ * A_ * 4; // scores offset
    const long long ba = (long long)b * A_ + a;

    int tag = 0;
    if (valid) {
        tag = g_tag[ba];
        if (tag) g_tag[ba] = 0;     // restore zero invariant for next replay
    }
    const int cnt = tag >> 16;
    int asg = (cnt == 1) ? (tag & 0xffff) - 1 : 0;

    // warp-cooperative resolution of conflicted anchors (cnt > 1)
    unsigned conf = __ballot_sync(0xffffffffu, cnt > 1);
    const int wbase = a - lane;                    // anchor of lane 0 in this warp
    while (conf) {
        const int src = __ffs(conf) - 1;
        conf &= conf - 1;
        const float4 abx = ((const float4*)anchors)[wbase + src];  // uniform -> broadcast
        // lane handles m = lane and m = lane + 32
        float4 g1 = s_gt[lane];
        float v1 = iou_box(g1.x, g1.y, g1.z, g1.w, abx.x, abx.y, abx.z, abx.w);
        float4 g2 = s_gt[lane + 32];
        float v2 = iou_box(g2.x, g2.y, g2.z, g2.w, abx.x, abx.y, abx.z, abx.w);
        // key = (~iou_bits, m): min key == (max iou, first m). iou >= +0.0 so
        // float bits are order-preserving and bit-equality == value-equality.
        unsigned long long k1 = ((unsigned long long)(~__float_as_uint(v1)) << 32) | (unsigned)lane;
        unsigned long long k2 = ((unsigned long long)(~__float_as_uint(v2)) << 32) | (unsigned)(lane + 32);
        unsigned long long k = (k2 < k1) ? k2 : k1;
        #pragma unroll
        for (int off = 16; off; off >>= 1) {
            unsigned long long o = __shfl_xor_sync(0xffffffffu, k, off);
            if (o < k) k = o;
        }
        if (lane == src) asg = (int)(k & 0xffffffffu);
    }

    if (valid) {
        const int bg = bg_ptr ? bg_ptr[0] : NC;
        int   label = bg;
        float sval  = 0.f;
        if (cnt > 0) {
            label = s_lab[asg];
            float4 p = ((const float4*)pred)[ba];
            float4 gg = s_gt[asg];
            sval = iou_box(gg.x, gg.y, gg.z, gg.w, p.x, p.y, p.z, p.w);
        }
        out[ba] = (float)label;                  // assigned_labels (as f32)
        ((float4*)(out + OFF1))[ba] = s_gt[asg]; // assigned_bboxes (gt[0] when bg)
        s_alab[t] = (cnt > 0 && label >= 0 && label < NC) ? label : -1;
        s_sval[t] = sval;
    }
    __syncthreads();

    // Phase 2: coalesced full score rows, written exactly once.
    int nA = A_ - a0; if (nA > 256) nA = 256;
    const int nvec = nA * (NC / 4);
    float4* srow = (float4*)(out + OFF2 + ((long long)b * A_ + a0) * NC);
    for (int i = t; i < nvec; i += 256) {
        const int al = i / (NC / 4);             // local anchor (const-div -> mulhi)
        const int c0 = (i - al * (NC / 4)) * 4;  // first class of this vector
        const int lab = s_alab[al];
        const float s = s_sval[al];
        float4 v;
        v.x = (lab == c0    ) ? s : 0.f;
        v.y = (lab == c0 + 1) ? s : 0.f;
        v.z = (lab == c0 + 2) ? s : 0.f;
        v.w = (lab == c0 + 3) ? s : 0.f;
        srow[i] = v;
    }
}

extern "C" void kernel_launch(void* const* d_in, const int* in_sizes, int n_in,
                              void* d_out, int out_size) {
    const float* anchors   = (const float*)d_in[0];
    const int*   gt_labels = (const int*)d_in[1];
    const float* gt_bboxes = (const float*)d_in[2];
    const float* pad_mask  = (const float*)d_in[3];
    const float* pred      = (const float*)d_in[4];
    const int*   bg_ptr    = (n_in > 5) ? (const int*)d_in[5] : nullptr;
    float* out = (float*)d_out;

    atss_topk_kernel<<<(B_ * M_) / 8, 256>>>(anchors, gt_bboxes, pad_mask);
    atss_assign_kernel<<<dim3((A_ + 255) / 256, B_), 256>>>(
        anchors, gt_labels, gt_bboxes, pred, bg_ptr, out);
}